// round 14
// baseline (speedup 1.0000x reference)
#include <cuda_runtime.h>
#include <cuda_bf16.h>
#include <cstdint>
#include <cstddef>

#define OUTD 8192
#define IND  8192
#define BSZ  32
#define SCALE (0.01f / 32.0f)

__device__ __forceinline__ uint32_t smem_u32(const void* p) {
    uint32_t a;
    asm("{ .reg .u64 t; cvta.to.shared.u64 t, %1; cvt.u32.u64 %0, t; }" : "=r"(a) : "l"(p));
    return a;
}

// pack two f32 -> bf16x2 in a u32 (lo = a, hi = b)
__device__ __forceinline__ uint32_t f32x2_to_bf16x2(float a, float b) {
    uint32_t r;
    asm("cvt.rn.bf16x2.f32 %0, %1, %2;" : "=r"(r) : "f"(b), "f"(a));
    return r;
}

__device__ __forceinline__ void cp_async16(uint32_t smem_dst, const void* gmem_src) {
    asm volatile("cp.async.cg.shared.global [%0], [%1], 16;"
                 :: "r"(smem_dst), "l"(gmem_src) : "memory");
}

__device__ __forceinline__ void ldmatrix_x4_trans(uint32_t& r0, uint32_t& r1, uint32_t& r2,
                                                  uint32_t& r3, uint32_t addr) {
    asm volatile("ldmatrix.sync.aligned.m8n8.x4.trans.shared.b16 {%0,%1,%2,%3}, [%4];"
                 : "=r"(r0), "=r"(r1), "=r"(r2), "=r"(r3) : "r"(addr));
}

__device__ __forceinline__ void mma_bf16(float* d, uint32_t a0, uint32_t a1, uint32_t a2,
                                         uint32_t a3, uint32_t b0, uint32_t b1) {
    asm volatile(
        "mma.sync.aligned.m16n8k16.row.col.f32.bf16.bf16.f32 "
        "{%0,%1,%2,%3}, {%4,%5,%6,%7}, {%8,%9}, {%0,%1,%2,%3};"
        : "+f"(d[0]), "+f"(d[1]), "+f"(d[2]), "+f"(d[3])
        : "r"(a0), "r"(a1), "r"(a2), "r"(a3), "r"(b0), "r"(b1));
}

// ---------------- single fused kernel ----------------
// CTA tile: 128(o = m) x 64(i = n).
//  1) cp.async-prefetch 32KB W tile (overlaps everything below)
//  2) load f32 pre/post slices (L2-resident), convert bf16, store K-major smem
//  3) ldmatrix.x4.trans -> mma (row.col), K=32 in 2 k16 steps
//  4) epilogue: clip(W + SCALE*D), float4, streaming stores
#define WST  272   // W smem row stride (256B data + 16B pad)
#define PST  272   // post smem row stride (128 bf16 = 256B + 16B pad)
#define BST  144   // pre  smem row stride (64 bf16 = 128B + 16B pad)
#define SM_W  (128 * WST)   // 34816
#define SM_P  (BSZ * PST)   // 8704
#define SM_Q  (BSZ * BST)   // 4608  (total 48128 <= 48KB static)

__global__ __launch_bounds__(256) void hebb_fused_kernel(
    const float* __restrict__ w,
    const float* __restrict__ pre,    // [BSZ, IND]
    const float* __restrict__ post,   // [BSZ, OUTD]
    float* __restrict__ out)
{
    __shared__ __align__(16) uint8_t smW[SM_W];
    __shared__ __align__(16) uint8_t smPost[SM_P];  // [b][o] bf16, K-major
    __shared__ __align__(16) uint8_t smPre[SM_Q];   // [b][i] bf16, K-major

    const int tid = threadIdx.x;
    const int wid = tid >> 5;
    const int lane = tid & 31;
    const int i0 = blockIdx.x * 64;
    const int o0 = blockIdx.y * 128;

    // ---- 1) W-tile prefetch first: 2048 x 16B cp.async ----
    const uint32_t smWb = smem_u32(smW);
#pragma unroll
    for (int s = tid; s < 2048; s += 256) {
        int row = s >> 4, seg = s & 15;
        cp_async16(smWb + row * WST + seg * 16,
                   w + (size_t)(o0 + row) * IND + i0 + seg * 4);
    }
    asm volatile("cp.async.commit_group;" ::: "memory");

    // ---- 2) fused operand load + f32->bf16 convert (K-major store) ----
#pragma unroll
    for (int t = tid; t < 1024; t += 256) {          // post: 32 rows x 32 float4
        int b = t >> 5, c4 = t & 31;
        float4 v = *reinterpret_cast<const float4*>(post + (size_t)b * OUTD + o0 + c4 * 4);
        uint2 h;
        h.x = f32x2_to_bf16x2(v.x, v.y);
        h.y = f32x2_to_bf16x2(v.z, v.w);
        *reinterpret_cast<uint2*>(smPost + b * PST + c4 * 8) = h;
    }
#pragma unroll
    for (int t = tid; t < 512; t += 256) {           // pre: 32 rows x 16 float4
        int b = t >> 4, c4 = t & 15;
        float4 v = *reinterpret_cast<const float4*>(pre + (size_t)b * IND + i0 + c4 * 4);
        uint2 h;
        h.x = f32x2_to_bf16x2(v.x, v.y);
        h.y = f32x2_to_bf16x2(v.z, v.w);
        *reinterpret_cast<uint2*>(smPre + b * BST + c4 * 8) = h;
    }
    __syncthreads();

    // ---- 3) mma with ldmatrix.trans (K-major operands) ----
    // A (m16k16): r0=(m0-7,k0-7) src(b0-7,o0-7); r1=(m8-15,k0-7) src(b0-7,o8-15);
    //             r2=(m0-7,k8-15) src(b8-15,o0-7); r3=(m8-15,k8-15)
    const uint32_t basePost = smem_u32(smPost);
    const uint32_t basePre  = smem_u32(smPre);
    const int a_b = ((lane >> 4) & 1) * 8 + (lane & 7);          // b row
    const int a_o = wid * 16 + ((lane >> 3) & 1) * 8;            // o col
    const uint32_t a_off = basePost + a_b * PST + a_o * 2;
    // B (n8k16 x2): r0=(n0-7,k0-7) src(b0-7,n0-7); r1=(n0-7,k8-15) src(b8-15,n0-7);
    //               r2=(n8-15,k0-7); r3=(n8-15,k8-15)
    const int b_b = ((lane >> 3) & 1) * 8 + (lane & 7);
    const int b_n = ((lane >> 4) & 1) * 8;
    const uint32_t b_off = basePre + b_b * BST + b_n * 2;

    float d[8][4];
#pragma unroll
    for (int f = 0; f < 8; f++)
#pragma unroll
        for (int q = 0; q < 4; q++) d[f][q] = 0.0f;

#pragma unroll
    for (int ks = 0; ks < 2; ks++) {                 // b rows 0-15 / 16-31
        uint32_t a0, a1, a2, a3;
        ldmatrix_x4_trans(a0, a1, a2, a3, a_off + ks * 16 * PST);
#pragma unroll
        for (int nf = 0; nf < 4; nf++) {
            uint32_t b0, b1, b2, b3;
            ldmatrix_x4_trans(b0, b1, b2, b3, b_off + nf * 32 + ks * 16 * BST);
            mma_bf16(d[2 * nf],     a0, a1, a2, a3, b0, b1);
            mma_bf16(d[2 * nf + 1], a0, a1, a2, a3, b2, b3);
        }
    }

    // ---- 4) wait W prefetch ----
    asm volatile("cp.async.wait_group 0;" ::: "memory");
    __syncthreads();

    // ---- 5) epilogue: shuffle to float4, W from smem, streaming STG.128 ----
    const int g  = lane >> 2;
    const int tq = lane & 3;
    const int j  = tq >> 1;
    const int s  = tq & 1;
    const int row_l = wid * 16 + g;

#pragma unroll
    for (int u = 0; u < 4; u++) {
        const int f0 = 2 * u, f1 = 2 * u + 1;
        const int myf = s ? f1 : f0;
        const int col_l = myf * 8 + j * 4;
#pragma unroll
        for (int h = 0; h < 2; h++) {
            float2 give;
            give.x = s ? d[f0][2 * h]     : d[f1][2 * h];
            give.y = s ? d[f0][2 * h + 1] : d[f1][2 * h + 1];
            unsigned long long gv = *reinterpret_cast<unsigned long long*>(&give);
            unsigned long long rv = __shfl_xor_sync(0xFFFFFFFFu, gv, 1);
            float2 recv = *reinterpret_cast<float2*>(&rv);

            float4 acc4;
            if (s == 0) {
                acc4.x = d[f0][2 * h]; acc4.y = d[f0][2 * h + 1];
                acc4.z = recv.x;       acc4.w = recv.y;
            } else {
                acc4.x = recv.x;       acc4.y = recv.y;
                acc4.z = d[f1][2 * h]; acc4.w = d[f1][2 * h + 1];
            }

            const int rl = row_l + h * 8;
            float4 wv = *reinterpret_cast<const float4*>(smW + rl * WST + col_l * 4);
            float4 ov;
            ov.x = __saturatef(fmaf(acc4.x, SCALE, wv.x));
            ov.y = __saturatef(fmaf(acc4.y, SCALE, wv.y));
            ov.z = __saturatef(fmaf(acc4.z, SCALE, wv.z));
            ov.w = __saturatef(fmaf(acc4.w, SCALE, wv.w));
            __stcs(reinterpret_cast<float4*>(out + (size_t)(o0 + rl) * IND + i0 + col_l), ov);
        }
    }
}

extern "C" void kernel_launch(void* const* d_in, const int* in_sizes, int n_in,
                              void* d_out, int out_size)
{
    const float* w    = (const float*)d_in[0];  // weights       [8192, 8192]
    const float* pre  = (const float*)d_in[1];  // pre_activity  [32, 8192]
    const float* post = (const float*)d_in[2];  // post_activity [32, 8192]
    float* out = (float*)d_out;                 // [8192, 8192] fp32

    dim3 grid(IND / 64, OUTD / 128);            // 128 x 64 = 8192 CTAs
    hebb_fused_kernel<<<grid, 256>>>(w, pre, post, out);
}

// round 17
// speedup vs baseline: 1.4146x; 1.4146x over previous
#include <cuda_runtime.h>
#include <cuda_bf16.h>
#include <cstdint>
#include <cstddef>

#define OUTD 8192
#define IND  8192
#define BSZ  32
#define SCALE (0.01f / 32.0f)

// bf16 transposed operand buffers: [dim][batch], k-contiguous
__device__ __align__(16) __nv_bfloat16 g_preT[(size_t)IND * BSZ];   // [i][b]
__device__ __align__(16) __nv_bfloat16 g_postT[(size_t)OUTD * BSZ]; // [o][b]

__device__ __forceinline__ uint32_t smem_u32(const void* p) {
    uint32_t a;
    asm("{ .reg .u64 t; cvta.to.shared.u64 t, %1; cvt.u32.u64 %0, t; }" : "=r"(a) : "l"(p));
    return a;
}

__device__ __forceinline__ void cp_async16(uint32_t smem_dst, const void* gmem_src) {
    asm volatile("cp.async.cg.shared.global [%0], [%1], 16;"
                 :: "r"(smem_dst), "l"(gmem_src) : "memory");
}

__device__ __forceinline__ void ldmatrix_x4(uint32_t& r0, uint32_t& r1, uint32_t& r2,
                                            uint32_t& r3, uint32_t addr) {
    asm volatile("ldmatrix.sync.aligned.m8n8.x4.shared.b16 {%0,%1,%2,%3}, [%4];"
                 : "=r"(r0), "=r"(r1), "=r"(r2), "=r"(r3) : "r"(addr));
}

__device__ __forceinline__ void mma_bf16(float* d, uint32_t a0, uint32_t a1, uint32_t a2,
                                         uint32_t a3, uint32_t b0, uint32_t b1) {
    asm volatile(
        "mma.sync.aligned.m16n8k16.row.col.f32.bf16.bf16.f32 "
        "{%0,%1,%2,%3}, {%4,%5,%6,%7}, {%8,%9}, {%0,%1,%2,%3};"
        : "+f"(d[0]), "+f"(d[1]), "+f"(d[2]), "+f"(d[3])
        : "r"(a0), "r"(a1), "r"(a2), "r"(a3), "r"(b0), "r"(b1));
}

// ---------------- pre-pass: f32 [B, N] -> bf16 transposed [N, B] ----------------
__global__ __launch_bounds__(256) void convert_kernel(const float* __restrict__ pre,
                                                      const float* __restrict__ post) {
    int idx = blockIdx.x * 256 + threadIdx.x;   // 0..65535
    int col = idx & 16383;
    int bg  = idx >> 14;                        // 0..3 (batches bg*8 .. bg*8+7)

    const float* src;
    __nv_bfloat16* dst;
    int c;
    if (col < IND) { src = pre;  dst = g_preT;  c = col; }
    else           { src = post; dst = g_postT; c = col - IND; }

    float v[8];
#pragma unroll
    for (int b = 0; b < 8; b++) v[b] = src[(size_t)(bg * 8 + b) * IND + c];

    __nv_bfloat162 h[4];
#pragma unroll
    for (int j = 0; j < 4; j++) h[j] = __floats2bfloat162_rn(v[2 * j], v[2 * j + 1]);

    *reinterpret_cast<uint4*>(dst + (size_t)c * BSZ + bg * 8) =
        *reinterpret_cast<const uint4*>(h);
}

// ---------------- main kernel ----------------
// CTA tile: 128(o = m) x 64(i = n). cp.async prefetches the 32KB W tile FIRST,
// overlapping DRAM W-fetch with operand load + mma. Epilogue: W from smem,
// streaming (evict-first) stores to out.
#define SMS  80    // operand smem row stride (64B data + 16B pad)
#define WST  272   // W smem row stride in bytes (256B data + 16B pad)
#define SM_W_BYTES (128 * WST)            // 34816
#define SM_A_BYTES (128 * SMS)            // 10240
#define SM_B_BYTES (64 * SMS)             // 5120
#define SM_TOTAL   (SM_W_BYTES + SM_A_BYTES + SM_B_BYTES)  // 50176

__global__ __launch_bounds__(256) void hebb_mma_kernel(
    const float* __restrict__ w, float* __restrict__ out)
{
    extern __shared__ __align__(16) uint8_t dynsm[];
    uint8_t* smW = dynsm;
    uint8_t* smA = dynsm + SM_W_BYTES;
    uint8_t* smB = dynsm + SM_W_BYTES + SM_A_BYTES;

    const int tid = threadIdx.x;
    const int wid = tid >> 5;
    const int lane = tid & 31;
    const int i0 = blockIdx.x * 64;
    const int o0 = blockIdx.y * 128;

    // ---- 1) issue W-tile prefetch immediately: 2048 x 16B cp.async ----
    const uint32_t smWb = smem_u32(smW);
#pragma unroll
    for (int s = tid; s < 2048; s += 256) {
        int row = s >> 4, seg = s & 15;          // 16 segs of 16B per 256B row
        cp_async16(smWb + row * WST + seg * 16,
                   w + (size_t)(o0 + row) * IND + i0 + seg * 4);
    }
    asm volatile("cp.async.commit_group;" ::: "memory");

    // ---- 2) operand tiles (L2-resident bf16) ----
    const uint4* Ag = reinterpret_cast<const uint4*>(g_postT + (size_t)o0 * BSZ);
    const uint4* Bg = reinterpret_cast<const uint4*>(g_preT  + (size_t)i0 * BSZ);
#pragma unroll
    for (int t = tid; t < 512; t += 256) {
        int row = t >> 2, c = t & 3;
        *reinterpret_cast<uint4*>(smA + row * SMS + c * 16) = Ag[t];
    }
    {
        int row = tid >> 2, c = tid & 3;
        *reinterpret_cast<uint4*>(smB + row * SMS + c * 16) = Bg[tid];
    }
    __syncthreads();

    const uint32_t baseA = smem_u32(smA);
    const uint32_t baseB = smem_u32(smB);

    const int a_row = wid * 16 + ((lane >> 3) & 1) * 8 + (lane & 7);
    const uint32_t a_off = baseA + a_row * SMS + (lane >> 4) * 16;
    const int b_row = ((lane >> 4) & 1) * 8 + (lane & 7);
    const uint32_t b_off = baseB + b_row * SMS + ((lane >> 3) & 1) * 16;

    float d[8][4];
#pragma unroll
    for (int f = 0; f < 8; f++)
#pragma unroll
        for (int q = 0; q < 4; q++) d[f][q] = 0.0f;

    // ---- 3) mma (overlaps with in-flight W prefetch) ----
#pragma unroll
    for (int ks = 0; ks < 2; ks++) {
        uint32_t a0, a1, a2, a3;
        ldmatrix_x4(a0, a1, a2, a3, a_off + ks * 32);
#pragma unroll
        for (int nf = 0; nf < 4; nf++) {
            uint32_t b0, b1, b2, b3;
            ldmatrix_x4(b0, b1, b2, b3, b_off + nf * 16 * SMS + ks * 32);
            mma_bf16(d[2 * nf],     a0, a1, a2, a3, b0, b1);
            mma_bf16(d[2 * nf + 1], a0, a1, a2, a3, b2, b3);
        }
    }

    // ---- 4) wait W prefetch ----
    asm volatile("cp.async.wait_group 0;" ::: "memory");
    __syncthreads();

    // ---- 5) epilogue: shuffle to float4, W from smem, streaming STG.128 ----
    const int g  = lane >> 2;
    const int tq = lane & 3;
    const int j  = tq >> 1;
    const int s  = tq & 1;
    const int row_l = wid * 16 + g;

#pragma unroll
    for (int u = 0; u < 4; u++) {
        const int f0 = 2 * u, f1 = 2 * u + 1;
        const int myf = s ? f1 : f0;
        const int col_l = myf * 8 + j * 4;       // 0..60, step 4
#pragma unroll
        for (int h = 0; h < 2; h++) {
            float2 give;
            give.x = s ? d[f0][2 * h]     : d[f1][2 * h];
            give.y = s ? d[f0][2 * h + 1] : d[f1][2 * h + 1];
            unsigned long long gv = *reinterpret_cast<unsigned long long*>(&give);
            unsigned long long rv = __shfl_xor_sync(0xFFFFFFFFu, gv, 1);
            float2 recv = *reinterpret_cast<float2*>(&rv);

            float4 acc4;
            if (s == 0) {
                acc4.x = d[f0][2 * h]; acc4.y = d[f0][2 * h + 1];
                acc4.z = recv.x;       acc4.w = recv.y;
            } else {
                acc4.x = recv.x;       acc4.y = recv.y;
                acc4.z = d[f1][2 * h]; acc4.w = d[f1][2 * h + 1];
            }

            const int rl = row_l + h * 8;
            float4 wv = *reinterpret_cast<const float4*>(smW + rl * WST + col_l * 4);
            float4 ov;
            ov.x = __saturatef(fmaf(acc4.x, SCALE, wv.x));
            ov.y = __saturatef(fmaf(acc4.y, SCALE, wv.y));
            ov.z = __saturatef(fmaf(acc4.z, SCALE, wv.z));
            ov.w = __saturatef(fmaf(acc4.w, SCALE, wv.w));
            __stcs(reinterpret_cast<float4*>(out + (size_t)(o0 + rl) * IND + i0 + col_l), ov);
        }
    }
}

extern "C" void kernel_launch(void* const* d_in, const int* in_sizes, int n_in,
                              void* d_out, int out_size)
{
    const float* w    = (const float*)d_in[0];  // weights       [8192, 8192]
    const float* pre  = (const float*)d_in[1];  // pre_activity  [32, 8192]
    const float* post = (const float*)d_in[2];  // post_activity [32, 8192]
    float* out = (float*)d_out;                 // [8192, 8192] fp32

    // Opt in to >48KB dynamic smem (host attribute set; deterministic, capture-safe)
    cudaFuncSetAttribute(hebb_mma_kernel,
                         cudaFuncAttributeMaxDynamicSharedMemorySize, SM_TOTAL);

    convert_kernel<<<256, 256>>>(pre, post);
    dim3 grid(IND / 64, OUTD / 128);            // 128 x 64 = 8192 CTAs
    hebb_mma_kernel<<<grid, 256, SM_TOTAL>>>(w, out);
}